// round 4
// baseline (speedup 1.0000x reference)
#include <cuda_runtime.h>
#include <cuda_bf16.h>
#include <cstdint>

// ---------------------------------------------------------------------------
// bwd_mpgnn: 6-level GNN stack. Every matmul is C = tanh((A [+A2 for k<K2]) @ W^T + b).
// bf16x3 split GEMM (hi+lo) on mma.sync.m16n8k16, fp32 accumulate -> ~1e-4 accuracy.
// ---------------------------------------------------------------------------

#define NN 32768
#define PAD 40                        // smem row stride in bf16 elems (conflict-free ldmatrix)
#define TILE_BYTES (128 * PAD * 2)    // 10240 B per 128x32 bf16 tile
#define SMEM_BYTES (8 * TILE_BYTES)   // Ah/Al/Bh/Bl x 2 stages = 81920 B

// scratch (static device globals: no runtime allocation allowed)
__device__ float g_E [NN * 256];
__device__ float g_B0[NN * 512];
__device__ float g_B1[NN * 512];
__device__ float g_T0[NN * 256];
__device__ float g_T1[NN * 256];
__device__ float g_T2[NN * 256];
__device__ float g_X2[NN * 512];
__device__ float g_M [NN * 256];

// ---------------- accurate rational tanh (XLA/Eigen) -----------------------
__device__ __forceinline__ float fast_tanh(float x) {
    const float c = 7.90531110763549805f;
    x = fminf(fmaxf(x, -c), c);
    const float x2 = x * x;
    float p = fmaf(x2, -2.76076847742355e-16f, 2.00018790482477e-13f);
    p = fmaf(x2, p, -8.60467152213735e-11f);
    p = fmaf(x2, p, 5.12229709037114e-08f);
    p = fmaf(x2, p, 1.48572235717979e-05f);
    p = fmaf(x2, p, 6.37261928875436e-04f);
    p = fmaf(x2, p, 4.89352455891786e-03f);
    p = x * p;
    float q = fmaf(x2, 1.19825839466702e-06f, 1.18534705686654e-04f);
    q = fmaf(x2, q, 2.26843463243900e-03f);
    q = fmaf(x2, q, 4.89352518554385e-03f);
    return p / q;
}

// ---------------- mma / ldmatrix helpers -----------------------------------
__device__ __forceinline__ void ldm_x4(uint32_t a, uint32_t& r0, uint32_t& r1,
                                       uint32_t& r2, uint32_t& r3) {
    asm volatile("ldmatrix.sync.aligned.m8n8.x4.shared.b16 {%0,%1,%2,%3}, [%4];\n"
                 : "=r"(r0), "=r"(r1), "=r"(r2), "=r"(r3) : "r"(a));
}
__device__ __forceinline__ void ldm_x2(uint32_t a, uint32_t& r0, uint32_t& r1) {
    asm volatile("ldmatrix.sync.aligned.m8n8.x2.shared.b16 {%0,%1}, [%2];\n"
                 : "=r"(r0), "=r"(r1) : "r"(a));
}
__device__ __forceinline__ void mma_bf16(float* c, const uint32_t* a, const uint32_t* b) {
    asm volatile("mma.sync.aligned.m16n8k16.row.col.f32.bf16.bf16.f32 "
                 "{%0,%1,%2,%3}, {%4,%5,%6,%7}, {%8,%9}, {%0,%1,%2,%3};\n"
                 : "+f"(c[0]), "+f"(c[1]), "+f"(c[2]), "+f"(c[3])
                 : "r"(a[0]), "r"(a[1]), "r"(a[2]), "r"(a[3]), "r"(b[0]), "r"(b[1]));
}

__device__ __forceinline__ uint32_t pack2(__nv_bfloat16 a, __nv_bfloat16 b) {
    return ((uint32_t)__bfloat16_as_ushort(b) << 16) | (uint32_t)__bfloat16_as_ushort(a);
}

__device__ __forceinline__ void store_split4(char* hi, char* lo, int r, int kq, float4 v) {
    __nv_bfloat16 h0 = __float2bfloat16_rn(v.x), h1 = __float2bfloat16_rn(v.y),
                  h2 = __float2bfloat16_rn(v.z), h3 = __float2bfloat16_rn(v.w);
    __nv_bfloat16 l0 = __float2bfloat16_rn(v.x - __bfloat162float(h0));
    __nv_bfloat16 l1 = __float2bfloat16_rn(v.y - __bfloat162float(h1));
    __nv_bfloat16 l2 = __float2bfloat16_rn(v.z - __bfloat162float(h2));
    __nv_bfloat16 l3 = __float2bfloat16_rn(v.w - __bfloat162float(h3));
    const uint32_t off = (uint32_t)(r * PAD + kq) * 2u;
    *(uint2*)(hi + off) = make_uint2(pack2(h0, h1), pack2(h2, h3));
    *(uint2*)(lo + off) = make_uint2(pack2(l0, l1), pack2(l2, l3));
}

// ---------------------------------------------------------------------------
// C[M,Nout] = tanh( (A [+A2 for k<K2]) @ W^T + bias )
// A:[M,K] stride lda. W:[Nout,K] stride ldw (allows K-major sub-views).
// BM=BN=128, BK=32, 256 threads (8 warps, 2x4), warp tile 64x32.
// ---------------------------------------------------------------------------
__global__ __launch_bounds__(256, 1) void gemm_tanh(
    const float* __restrict__ A, int lda,
    const float* __restrict__ A2, int lda2, int K2,
    const float* __restrict__ W, int ldw,
    const float* __restrict__ bias,
    float* __restrict__ C, int ldc, int K)
{
    extern __shared__ char smem[];
    const int tid  = threadIdx.x;
    const int lane = tid & 31;
    const int wid  = tid >> 5;
    const int wm   = wid >> 2;   // 0..1
    const int wn   = wid & 3;    // 0..3
    const int mBase = blockIdx.x * 128;
    const int nBase = blockIdx.y * 128;
    const uint32_t sb = (uint32_t)__cvta_generic_to_shared(smem);

    float acc[4][4][4];
#pragma unroll
    for (int i = 0; i < 4; i++)
#pragma unroll
        for (int j = 0; j < 4; j++)
#pragma unroll
            for (int k = 0; k < 4; k++) acc[i][j][k] = 0.f;

    int row[4], kq[4];
#pragma unroll
    for (int i = 0; i < 4; i++) {
        const int ci = tid + (i << 8);
        row[i] = ci >> 3;            // 0..127
        kq[i]  = (ci & 7) << 2;      // 0,4,...,28
    }

    float4 ra[4], rb[4];
    const int T = K >> 5;

    auto gload = [&](int t) {
        const int k0 = t << 5;
        const bool res = (A2 != nullptr) && (k0 < K2);
#pragma unroll
        for (int i = 0; i < 4; i++) {
            ra[i] = *(const float4*)(A + (size_t)(mBase + row[i]) * lda + k0 + kq[i]);
            if (res) {
                const float4 r2 = *(const float4*)(A2 + (size_t)(mBase + row[i]) * lda2 + k0 + kq[i]);
                ra[i].x += r2.x; ra[i].y += r2.y; ra[i].z += r2.z; ra[i].w += r2.w;
            }
            rb[i] = *(const float4*)(W + (size_t)(nBase + row[i]) * ldw + k0 + kq[i]);
        }
    };

    auto sstore = [&](int s) {
        char* base = smem + s * 4 * TILE_BYTES;
#pragma unroll
        for (int i = 0; i < 4; i++) {
            store_split4(base,                  base + TILE_BYTES,     row[i], kq[i], ra[i]);
            store_split4(base + 2 * TILE_BYTES, base + 3 * TILE_BYTES, row[i], kq[i], rb[i]);
        }
    };

    auto compute = [&](int s) {
        const uint32_t ab = sb + (uint32_t)(s * 4 * TILE_BYTES);
        const uint32_t bb = ab + 2 * TILE_BYTES;
#pragma unroll
        for (int ks = 0; ks < 2; ks++) {
            uint32_t ah[4][4], al[4][4], bh[4][2], bl[4][2];
            const int r16 = ((lane >> 3) & 1) * 8 + (lane & 7);
            const int kofA = (lane >> 4) * 8;
#pragma unroll
            for (int mf = 0; mf < 4; mf++) {
                const uint32_t addr = ab +
                    (uint32_t)(((wm * 64 + mf * 16 + r16) * PAD + ks * 16 + kofA) * 2);
                ldm_x4(addr,              ah[mf][0], ah[mf][1], ah[mf][2], ah[mf][3]);
                ldm_x4(addr + TILE_BYTES, al[mf][0], al[mf][1], al[mf][2], al[mf][3]);
            }
            const int r8  = lane & 7;
            const int kofB = ((lane >> 3) & 1) * 8;
#pragma unroll
            for (int nf = 0; nf < 4; nf++) {
                const uint32_t addr = bb +
                    (uint32_t)(((wn * 32 + nf * 8 + r8) * PAD + ks * 16 + kofB) * 2);
                ldm_x2(addr,              bh[nf][0], bh[nf][1]);
                ldm_x2(addr + TILE_BYTES, bl[nf][0], bl[nf][1]);
            }
#pragma unroll
            for (int mf = 0; mf < 4; mf++)
#pragma unroll
                for (int nf = 0; nf < 4; nf++) {
                    mma_bf16(acc[mf][nf], ah[mf], bh[nf]);
                    mma_bf16(acc[mf][nf], ah[mf], bl[nf]);
                    mma_bf16(acc[mf][nf], al[mf], bh[nf]);
                }
        }
    };

    gload(0);
    sstore(0);
    __syncthreads();
    for (int t = 0; t < T; t++) {
        if (t + 1 < T) gload(t + 1);
        compute(t & 1);
        if (t + 1 < T) {
            __syncthreads();
            sstore((t + 1) & 1);
            __syncthreads();
        }
    }

    // epilogue: bias + tanh, fp32 store
#pragma unroll
    for (int mf = 0; mf < 4; mf++) {
        const int r0 = mBase + wm * 64 + mf * 16 + (lane >> 2);
#pragma unroll
        for (int nf = 0; nf < 4; nf++) {
            const int c0 = nBase + wn * 32 + nf * 8 + (lane & 3) * 2;
            const float b0 = __ldg(bias + c0), b1 = __ldg(bias + c0 + 1);
            float2 v0 = make_float2(fast_tanh(acc[mf][nf][0] + b0),
                                    fast_tanh(acc[mf][nf][1] + b1));
            float2 v1 = make_float2(fast_tanh(acc[mf][nf][2] + b0),
                                    fast_tanh(acc[mf][nf][3] + b1));
            *(float2*)(C + (size_t)r0 * ldc + c0)       = v0;
            *(float2*)(C + (size_t)(r0 + 8) * ldc + c0) = v1;
        }
    }
}

// msgs[n,:] = sum_{k<8} src[idx[n,k], :]
__global__ __launch_bounds__(256) void gather_sum(
    const float* __restrict__ src, const int* __restrict__ idx, float* __restrict__ dst)
{
    const int node = blockIdx.x * 4 + (threadIdx.x >> 6);
    const int lane = threadIdx.x & 63;
    const int* ip = idx + node * 8;
    float4 s = make_float4(0.f, 0.f, 0.f, 0.f);
#pragma unroll
    for (int k = 0; k < 8; k++) {
        const float4 v = *(const float4*)(src + (size_t)ip[k] * 256 + lane * 4);
        s.x += v.x; s.y += v.y; s.z += v.z; s.w += v.w;
    }
    *(float4*)(dst + (size_t)node * 256 + lane * 4) = s;
}

extern "C" void kernel_launch(void* const* d_in, const int* in_sizes, int n_in,
                              void* d_out, int out_size)
{
    const float* feats = (const float*)d_in[0];
    const int*   pred  = (const int*)  d_in[1];
    const float* We    = (const float*)d_in[2];
    const float* be    = (const float*)d_in[3];
    const float* rsW1  = (const float*)d_in[4];
    const float* rsb1  = (const float*)d_in[5];
    const float* rsW2  = (const float*)d_in[6];
    const float* rsb2  = (const float*)d_in[7];
    const float* rsW3  = (const float*)d_in[8];
    const float* rsb3  = (const float*)d_in[9];
    const float* rcW1  = (const float*)d_in[10];
    const float* rcb1  = (const float*)d_in[11];
    const float* rcW2  = (const float*)d_in[12];
    const float* rcb2  = (const float*)d_in[13];
    const float* rcW3  = (const float*)d_in[14];
    const float* rcb3  = (const float*)d_in[15];
    float* out = (float*)d_out;

    float *E, *B0, *B1, *T0, *T1, *T2, *X2, *M;
    cudaGetSymbolAddress((void**)&E,  g_E);
    cudaGetSymbolAddress((void**)&B0, g_B0);
    cudaGetSymbolAddress((void**)&B1, g_B1);
    cudaGetSymbolAddress((void**)&T0, g_T0);
    cudaGetSymbolAddress((void**)&T1, g_T1);
    cudaGetSymbolAddress((void**)&T2, g_T2);
    cudaGetSymbolAddress((void**)&X2, g_X2);
    cudaGetSymbolAddress((void**)&M,  g_M);

    cudaFuncSetAttribute(gemm_tanh, cudaFuncAttributeMaxDynamicSharedMemorySize, SMEM_BYTES);

    auto G = [&](const float* A, int lda, const float* A2, int lda2, int K2,
                 const float* W, int ldw, const float* b, float* C, int ldc,
                 int K, int Nout) {
        dim3 grid(NN / 128, Nout / 128);
        gemm_tanh<<<grid, 256, SMEM_BYTES>>>(A, lda, A2, lda2, K2, W, ldw, b, C, ldc, K);
    };

    // level 0: out[0] = tanh(feats[0] @ We^T + be)
    G(feats, 32, nullptr, 0, 0, We, 32, be, out, 256, 32, 256);

    for (int l = 1; l < 6; l++) {
        const int d  = (l - 1 < 2) ? (l - 1) : 2;
        const int i1 = 3 + d, i2 = 9 + d, i3 = d, i4 = 6 + d;
        const int sA = 2 * d, sB = 2 * d + 1;

        // embed
        G(feats + (size_t)l * NN * 32, 32, nullptr, 0, 0, We, 32, be, E, 256, 32, 256);

        // big(3+d) on concat(e, 0): layer1 K=256 (zero half skipped)
        G(E,  256, nullptr, 0, 0,  rcW1 + (size_t)i1 * 262144, 512, rcb1 + i1 * 512, B0, 512, 256, 512);
        G(B0, 512, nullptr, 0, 0,  rcW2 + (size_t)i1 * 262144, 512, rcb2 + i1 * 512, B1, 512, 512, 512);
        G(B1, 512, E, 256, 256,    rcW3 + (size_t)i1 * 131072, 512, rcb3 + i1 * 256, T0, 256, 512, 256);
        // small(9+d) -> e2 into X2[:, 0:256]
        G(T0, 256, nullptr, 0, 0,  rsW1 + (size_t)i2 * 65536, 256, rsb1 + i2 * 256, T1, 256, 256, 256);
        G(T1, 256, nullptr, 0, 0,  rsW2 + (size_t)i2 * 65536, 256, rsb2 + i2 * 256, T2, 256, 256, 256);
        G(T2, 256, T0, 256, 256,   rsW3 + (size_t)i2 * 65536, 256, rsb3 + i2 * 256, X2, 512, 256, 256);

        // messages from previous level's final embeds
        gather_sum<<<NN / 4, 256>>>(out + (size_t)(l - 1) * NN * 256,
                                    pred + (size_t)(l - 1) * NN * 8, M);
        // small(2d)
        G(M,  256, nullptr, 0, 0,  rsW1 + (size_t)sA * 65536, 256, rsb1 + sA * 256, T1, 256, 256, 256);
        G(T1, 256, nullptr, 0, 0,  rsW2 + (size_t)sA * 65536, 256, rsb2 + sA * 256, T2, 256, 256, 256);
        G(T2, 256, M, 256, 256,    rsW3 + (size_t)sA * 65536, 256, rsb3 + sA * 256, T0, 256, 256, 256);
        // small(2d+1) -> r into X2[:, 256:512]
        G(T0, 256, nullptr, 0, 0,  rsW1 + (size_t)sB * 65536, 256, rsb1 + sB * 256, T1, 256, 256, 256);
        G(T1, 256, nullptr, 0, 0,  rsW2 + (size_t)sB * 65536, 256, rsb2 + sB * 256, T2, 256, 256, 256);
        G(T2, 256, T0, 256, 256,   rsW3 + (size_t)sB * 65536, 256, rsb3 + sB * 256, X2 + 256, 512, 256, 256);

        // big(d) on x2 = concat(e2, r)
        G(X2, 512, nullptr, 0, 0,  rcW1 + (size_t)i3 * 262144, 512, rcb1 + i3 * 512, B0, 512, 512, 512);
        G(B0, 512, nullptr, 0, 0,  rcW2 + (size_t)i3 * 262144, 512, rcb2 + i3 * 512, B1, 512, 512, 512);
        G(B1, 512, X2, 512, 512,   rcW3 + (size_t)i3 * 131072, 512, rcb3 + i3 * 256, T0, 256, 512, 256);
        // small(6+d) -> out[l]
        G(T0, 256, nullptr, 0, 0,  rsW1 + (size_t)i4 * 65536, 256, rsb1 + i4 * 256, T1, 256, 256, 256);
        G(T1, 256, nullptr, 0, 0,  rsW2 + (size_t)i4 * 65536, 256, rsb2 + i4 * 256, T2, 256, 256, 256);
        G(T2, 256, T0, 256, 256,   rsW3 + (size_t)i4 * 65536, 256, rsb3 + i4 * 256,
          out + (size_t)l * NN * 256, 256, 256, 256);
    }
}

// round 6
// speedup vs baseline: 1.0853x; 1.0853x over previous
#include <cuda_runtime.h>
#include <cuda_bf16.h>
#include <cstdint>

// ---------------------------------------------------------------------------
// bwd_mpgnn: 6-level GNN stack. Every matmul is C = tanh(A @ W^T + b) with
// residuals folded into producer epilogues. All GEMM operands pre-split into
// bf16 hi/lo planes; GEMM mainloop = cp.async(4-stage) -> ldmatrix -> mma
// (bf16x3: hi*hi + hi*lo + lo*hi, fp32 accumulate).
// ---------------------------------------------------------------------------

#define NN 32768
#define PAD 40                        // smem row stride in bf16 elems (conflict-free ldmatrix)
#define TILE_BYTES (128 * PAD * 2)    // 10240 B per 128x32 bf16 plane
#define STAGES 4
#define SMEM_BYTES (STAGES * 4 * TILE_BYTES)   // 163840 B

typedef __nv_bfloat16 bf16;

// ---------------- weight / input split planes ------------------------------
__device__ bf16 g_WeH[8192],      g_WeL[8192];
__device__ bf16 g_fH[6 * NN * 32], g_fL[6 * NN * 32];
__device__ bf16 g_s1H[786432], g_s1L[786432];
__device__ bf16 g_s2H[786432], g_s2L[786432];
__device__ bf16 g_s3H[786432], g_s3L[786432];
__device__ bf16 g_c1H[1572864], g_c1L[1572864];
__device__ bf16 g_c2H[1572864], g_c2L[1572864];
__device__ bf16 g_c3H[786432],  g_c3L[786432];

// ---------------- activation planes ----------------------------------------
__device__ bf16 g_PAh[NN * 512], g_PAl[NN * 512];
__device__ bf16 g_PBh[NN * 512], g_PBl[NN * 512];
__device__ bf16 g_X2h[NN * 512], g_X2l[NN * 512];
__device__ bf16 g_Eh [NN * 256], g_El [NN * 256];
__device__ bf16 g_T0h[NN * 256], g_T0l[NN * 256];
__device__ bf16 g_T1h[NN * 256], g_T1l[NN * 256];
__device__ bf16 g_T2h[NN * 256], g_T2l[NN * 256];
__device__ bf16 g_Mh [NN * 256], g_Ml [NN * 256];
__device__ float g_Ef [NN * 256];
__device__ float g_T0f[NN * 256];
__device__ float g_Mf [NN * 256];
__device__ float g_X2f[NN * 512];

// ---------------- accurate rational tanh (XLA/Eigen) -----------------------
__device__ __forceinline__ float fast_tanh(float x) {
    const float c = 7.90531110763549805f;
    x = fminf(fmaxf(x, -c), c);
    const float x2 = x * x;
    float p = fmaf(x2, -2.76076847742355e-16f, 2.00018790482477e-13f);
    p = fmaf(x2, p, -8.60467152213735e-11f);
    p = fmaf(x2, p, 5.12229709037114e-08f);
    p = fmaf(x2, p, 1.48572235717979e-05f);
    p = fmaf(x2, p, 6.37261928875436e-04f);
    p = fmaf(x2, p, 4.89352455891786e-03f);
    p = x * p;
    float q = fmaf(x2, 1.19825839466702e-06f, 1.18534705686654e-04f);
    q = fmaf(x2, q, 2.26843463243900e-03f);
    q = fmaf(x2, q, 4.89352518554385e-03f);
    return p / q;
}

// ---------------- mma / ldmatrix helpers -----------------------------------
__device__ __forceinline__ void ldm_x4(uint32_t a, uint32_t& r0, uint32_t& r1,
                                       uint32_t& r2, uint32_t& r3) {
    asm volatile("ldmatrix.sync.aligned.m8n8.x4.shared.b16 {%0,%1,%2,%3}, [%4];\n"
                 : "=r"(r0), "=r"(r1), "=r"(r2), "=r"(r3) : "r"(a));
}
__device__ __forceinline__ void ldm_x2(uint32_t a, uint32_t& r0, uint32_t& r1) {
    asm volatile("ldmatrix.sync.aligned.m8n8.x2.shared.b16 {%0,%1}, [%2];\n"
                 : "=r"(r0), "=r"(r1) : "r"(a));
}
__device__ __forceinline__ void mma_bf16(float* c, const uint32_t* a, const uint32_t* b) {
    asm volatile("mma.sync.aligned.m16n8k16.row.col.f32.bf16.bf16.f32 "
                 "{%0,%1,%2,%3}, {%4,%5,%6,%7}, {%8,%9}, {%0,%1,%2,%3};\n"
                 : "+f"(c[0]), "+f"(c[1]), "+f"(c[2]), "+f"(c[3])
                 : "r"(a[0]), "r"(a[1]), "r"(a[2]), "r"(a[3]), "r"(b[0]), "r"(b[1]));
}
__device__ __forceinline__ uint32_t pack2(bf16 a, bf16 b) {
    return ((uint32_t)__bfloat16_as_ushort(b) << 16) | (uint32_t)__bfloat16_as_ushort(a);
}
__device__ __forceinline__ uint32_t split_hi(float2 v, uint32_t& lo) {
    bf16 h0 = __float2bfloat16_rn(v.x), h1 = __float2bfloat16_rn(v.y);
    bf16 l0 = __float2bfloat16_rn(v.x - __bfloat162float(h0));
    bf16 l1 = __float2bfloat16_rn(v.y - __bfloat162float(h1));
    lo = pack2(l0, l1);
    return pack2(h0, h1);
}

// ---------------------------------------------------------------------------
// C = tanh(A @ W^T + bias) [+R on cols<Rcols, added after tanh]
// Outputs (any may be null): Cf fp32, (Ch,Cl) bf16 split planes.
// A given as split planes (Ah,Al)[M,K] stride lda; W as (Wh,Wl)[Nout,K] stride ldw.
// BM=BN=128, BK=32, 256 threads (8 warps 2x4), warp tile 64x32. 4-stage cp.async.
// ---------------------------------------------------------------------------
__global__ __launch_bounds__(256, 1) void gemm_tanh(
    const bf16* __restrict__ Ah, const bf16* __restrict__ Al, int lda,
    const bf16* __restrict__ Wh, const bf16* __restrict__ Wl, int ldw,
    const float* __restrict__ bias,
    const float* __restrict__ R, int ldr, int Rcols,
    float* __restrict__ Cf,
    bf16* __restrict__ Ch, bf16* __restrict__ Cl,
    int ldc, int K)
{
    extern __shared__ char smem[];
    const int tid  = threadIdx.x;
    const int lane = tid & 31;
    const int wid  = tid >> 5;
    const int wm   = wid >> 2;   // 0..1
    const int wn   = wid & 3;    // 0..3
    const int mBase = blockIdx.x * 128;
    const int nBase = blockIdx.y * 128;
    const uint32_t sb = (uint32_t)__cvta_generic_to_shared(smem);

    float acc[4][4][4];
#pragma unroll
    for (int i = 0; i < 4; i++)
#pragma unroll
        for (int j = 0; j < 4; j++)
#pragma unroll
            for (int k = 0; k < 4; k++) acc[i][j][k] = 0.f;

    const int T = K >> 5;
    const int seg  = tid & 3;            // 16B segment within 64B row chunk
    const int rhalf = tid >> 2;          // 0..63

    auto issue = [&](int t) {
        const int k0 = (t << 5) + seg * 8;
        const uint32_t stb = sb + (uint32_t)((t % STAGES) * 4 * TILE_BYTES);
#pragma unroll
        for (int i = 0; i < 8; i++) {
            const int plane = i >> 1;                 // 0:Ah 1:Al 2:Wh 3:Wl
            const int row   = (i & 1) * 64 + rhalf;   // 0..127
            const uint32_t dst = stb + (uint32_t)(plane * TILE_BYTES + row * (PAD * 2) + seg * 16);
            const bf16* src;
            if      (plane == 0) src = Ah + (size_t)(mBase + row) * lda + k0;
            else if (plane == 1) src = Al + (size_t)(mBase + row) * lda + k0;
            else if (plane == 2) src = Wh + (size_t)(nBase + row) * ldw + k0;
            else                 src = Wl + (size_t)(nBase + row) * ldw + k0;
            asm volatile("cp.async.cg.shared.global [%0], [%1], 16;\n" :: "r"(dst), "l"(src));
        }
    };

    auto compute = [&](int s) {
        const uint32_t ab = sb + (uint32_t)(s * 4 * TILE_BYTES);
        const uint32_t bb = ab + 2 * TILE_BYTES;
#pragma unroll
        for (int ks = 0; ks < 2; ks++) {
            uint32_t ah[4][4], al[4][4], bh[4][2], bl[4][2];
            const int r16  = ((lane >> 3) & 1) * 8 + (lane & 7);
            const int kofA = (lane >> 4) * 8;
#pragma unroll
            for (int mf = 0; mf < 4; mf++) {
                const uint32_t addr = ab +
                    (uint32_t)(((wm * 64 + mf * 16 + r16) * PAD + ks * 16 + kofA) * 2);
                ldm_x4(addr,              ah[mf][0], ah[mf][1], ah[mf][2], ah[mf][3]);
                ldm_x4(addr + TILE_BYTES, al[mf][0], al[mf][1], al[mf][2], al[mf][3]);
            }
            const int r8   = lane & 7;
            const int kofB = ((lane >> 3) & 1) * 8;
#pragma unroll
            for (int nf = 0; nf < 4; nf++) {
                const uint32_t addr = bb +
                    (uint32_t)(((wn * 32 + nf * 8 + r8) * PAD + ks * 16 + kofB) * 2);
                ldm_x2(addr,              bh[nf][0], bh[nf][1]);
                ldm_x2(addr + TILE_BYTES, bl[nf][0], bl[nf][1]);
            }
#pragma unroll
            for (int mf = 0; mf < 4; mf++)
#pragma unroll
                for (int nf = 0; nf < 4; nf++) {
                    mma_bf16(acc[mf][nf], ah[mf], bh[nf]);
                    mma_bf16(acc[mf][nf], ah[mf], bl[nf]);
                    mma_bf16(acc[mf][nf], al[mf], bh[nf]);
                }
        }
    };

    // prologue: fill STAGES-1 groups (empty commits keep the invariant exact)
#pragma unroll
    for (int s = 0; s < STAGES - 1; s++) {
        if (s < T) issue(s);
        asm volatile("cp.async.commit_group;\n" ::: "memory");
    }
    for (int t = 0; t < T; t++) {
        asm volatile("cp.async.wait_group %0;\n" :: "n"(STAGES - 2) : "memory");
        __syncthreads();
        compute(t % STAGES);
        const int nt = t + STAGES - 1;
        if (nt < T) issue(nt);
        asm volatile("cp.async.commit_group;\n" ::: "memory");
    }

    // epilogue: bias + tanh (+residual), write fp32 and/or split planes
#pragma unroll
    for (int mf = 0; mf < 4; mf++) {
        const int r0 = mBase + wm * 64 + mf * 16 + (lane >> 2);
#pragma unroll
        for (int nf = 0; nf < 4; nf++) {
            const int c0 = nBase + wn * 32 + nf * 8 + (lane & 3) * 2;
            const float b0 = __ldg(bias + c0), b1 = __ldg(bias + c0 + 1);
            float2 v0 = make_float2(fast_tanh(acc[mf][nf][0] + b0),
                                    fast_tanh(acc[mf][nf][1] + b1));
            float2 v1 = make_float2(fast_tanh(acc[mf][nf][2] + b0),
                                    fast_tanh(acc[mf][nf][3] + b1));
            if (R != nullptr && c0 < Rcols) {
                const float2 ra = *(const float2*)(R + (size_t)r0 * ldr + c0);
                const float2 rb = *(const float2*)(R + (size_t)(r0 + 8) * ldr + c0);
                v0.x += ra.x; v0.y += ra.y;
                v1.x += rb.x; v1.y += rb.y;
            }
            const size_t o0 = (size_t)r0 * ldc + c0;
            const size_t o1 = (size_t)(r0 + 8) * ldc + c0;
            if (Cf != nullptr) {
                *(float2*)(Cf + o0) = v0;
                *(float2*)(Cf + o1) = v1;
            }
            if (Ch != nullptr) {
                uint32_t lo0, lo1;
                const uint32_t hi0 = split_hi(v0, lo0);
                const uint32_t hi1 = split_hi(v1, lo1);
                *(uint32_t*)(Ch + o0) = hi0;  *(uint32_t*)(Cl + o0) = lo0;
                *(uint32_t*)(Ch + o1) = hi1;  *(uint32_t*)(Cl + o1) = lo1;
            }
        }
    }
}

// ---------------- fp32 -> bf16 hi/lo split ---------------------------------
__global__ __launch_bounds__(256) void split_fp32(
    const float* __restrict__ x, bf16* __restrict__ h, bf16* __restrict__ l, int n4)
{
    const int i = blockIdx.x * 256 + threadIdx.x;
    if (i >= n4) return;
    const float4 v = *(const float4*)(x + (size_t)i * 4);
    uint32_t lo0, lo1;
    const uint32_t hi0 = split_hi(make_float2(v.x, v.y), lo0);
    const uint32_t hi1 = split_hi(make_float2(v.z, v.w), lo1);
    *(uint2*)(h + (size_t)i * 4) = make_uint2(hi0, hi1);
    *(uint2*)(l + (size_t)i * 4) = make_uint2(lo0, lo1);
}

// msgs[n,:] = sum_{k<8} src[idx[n,k], :] ; writes fp32 + split planes
__global__ __launch_bounds__(256) void gather_sum(
    const float* __restrict__ src, const int* __restrict__ idx,
    float* __restrict__ dstf, bf16* __restrict__ dsth, bf16* __restrict__ dstl)
{
    const int node = blockIdx.x * 4 + (threadIdx.x >> 6);
    const int lane = threadIdx.x & 63;
    const int* ip = idx + node * 8;
    float4 s = make_float4(0.f, 0.f, 0.f, 0.f);
#pragma unroll
    for (int k = 0; k < 8; k++) {
        const float4 v = *(const float4*)(src + (size_t)ip[k] * 256 + lane * 4);
        s.x += v.x; s.y += v.y; s.z += v.z; s.w += v.w;
    }
    const size_t o = (size_t)node * 256 + lane * 4;
    *(float4*)(dstf + o) = s;
    uint32_t lo0, lo1;
    const uint32_t hi0 = split_hi(make_float2(s.x, s.y), lo0);
    const uint32_t hi1 = split_hi(make_float2(s.z, s.w), lo1);
    *(uint2*)(dsth + o) = make_uint2(hi0, hi1);
    *(uint2*)(dstl + o) = make_uint2(lo0, lo1);
}

extern "C" void kernel_launch(void* const* d_in, const int* in_sizes, int n_in,
                              void* d_out, int out_size)
{
    const float* feats = (const float*)d_in[0];
    const int*   pred  = (const int*)  d_in[1];
    const float* WeF   = (const float*)d_in[2];
    const float* be    = (const float*)d_in[3];
    const float* rsW1  = (const float*)d_in[4];
    const float* rsb1  = (const float*)d_in[5];
    const float* rsW2  = (const float*)d_in[6];
    const float* rsb2  = (const float*)d_in[7];
    const float* rsW3  = (const float*)d_in[8];
    const float* rsb3  = (const float*)d_in[9];
    const float* rcW1  = (const float*)d_in[10];
    const float* rcb1  = (const float*)d_in[11];
    const float* rcW2  = (const float*)d_in[12];
    const float* rcb2  = (const float*)d_in[13];
    const float* rcW3  = (const float*)d_in[14];
    const float* rcb3  = (const float*)d_in[15];
    float* out = (float*)d_out;

    // resolve device-global scratch
    bf16 *WeH,*WeL,*fH,*fL,*s1H,*s1L,*s2H,*s2L,*s3H,*s3L,*c1H,*c1L,*c2H,*c2L,*c3H,*c3L;
    bf16 *PAh,*PAl,*PBh,*PBl,*X2h,*X2l,*Eh,*El,*T0h,*T0l,*T1h,*T1l,*T2h,*T2l,*Mh,*Ml;
    float *Ef,*T0f,*Mf,*X2f;
    cudaGetSymbolAddress((void**)&WeH, g_WeH); cudaGetSymbolAddress((void**)&WeL, g_WeL);
    cudaGetSymbolAddress((void**)&fH,  g_fH);  cudaGetSymbolAddress((void**)&fL,  g_fL);
    cudaGetSymbolAddress((void**)&s1H, g_s1H); cudaGetSymbolAddress((void**)&s1L, g_s1L);
    cudaGetSymbolAddress((void**)&s2H, g_s2H); cudaGetSymbolAddress((void**)&s2L, g_s2L);
    cudaGetSymbolAddress((void**)&s3H, g_s3H); cudaGetSymbolAddress((void**)&s3L, g_s3L);
    cudaGetSymbolAddress((void**)&c1H, g_c1H); cudaGetSymbolAddress((void**)&c1L, g_c1L);
    cudaGetSymbolAddress((void**)&c2H, g_c2H); cudaGetSymbolAddress((void**)&c2L, g_c2L);
    cudaGetSymbolAddress((void**)&c3H, g_c3H); cudaGetSymbolAddress((void**)&c3L, g_c3L);
    cudaGetSymbolAddress((void**)&PAh, g_PAh); cudaGetSymbolAddress((void**)&PAl, g_PAl);
    cudaGetSymbolAddress((void**)&PBh, g_PBh); cudaGetSymbolAddress((void**)&PBl, g_PBl);
    cudaGetSymbolAddress((void**)&X2h, g_X2h); cudaGetSymbolAddress((void**)&X2l, g_X2l);
    cudaGetSymbolAddress((void**)&Eh,  g_Eh);  cudaGetSymbolAddress((void**)&El,  g_El);
    cudaGetSymbolAddress((void**)&T0h, g_T0h); cudaGetSymbolAddress((void**)&T0l, g_T0l);
    cudaGetSymbolAddress((void**)&T1h, g_T1h); cudaGetSymbolAddress((void**)&T1l, g_T1l);
    cudaGetSymbolAddress((void**)&T2h, g_T2h); cudaGetSymbolAddress((void**)&T2l, g_T2l);
    cudaGetSymbolAddress((void**)&Mh,  g_Mh);  cudaGetSymbolAddress((void**)&Ml,  g_Ml);
    cudaGetSymbolAddress((void**)&Ef,  g_Ef);  cudaGetSymbolAddress((void**)&T0f, g_T0f);
    cudaGetSymbolAddress((void**)&Mf,  g_Mf);  cudaGetSymbolAddress((void**)&X2f, g_X2f);

    cudaFuncSetAttribute(gemm_tanh, cudaFuncAttributeMaxDynamicSharedMemorySize, SMEM_BYTES);

    // pre-split weights + feats
    auto SP = [&](const float* s, bf16* h, bf16* l, int n) {
        split_fp32<<<(n / 4 + 255) / 256, 256>>>(s, h, l, n / 4);
    };
    SP(WeF, WeH, WeL, 8192);
    SP(feats, fH, fL, 6 * NN * 32);
    SP(rsW1, s1H, s1L, 786432);
    SP(rsW2, s2H, s2L, 786432);
    SP(rsW3, s3H, s3L, 786432);
    SP(rcW1, c1H, c1L, 1572864);
    SP(rcW2, c2H, c2L, 1572864);
    SP(rcW3, c3H, c3L, 786432);

    auto G = [&](const bf16* Ah, const bf16* Al, int lda,
                 const bf16* Wh, const bf16* Wl, int ldw,
                 const float* b,
                 const float* R, int ldr, int Rcols,
                 float* Cf, bf16* Ch, bf16* Cl, int ldc,
                 int K, int Nout) {
        dim3 grid(NN / 128, Nout / 128);
        gemm_tanh<<<grid, 256, SMEM_BYTES>>>(Ah, Al, lda, Wh, Wl, ldw, b,
                                             R, ldr, Rcols, Cf, Ch, Cl, ldc, K);
    };

    // level 0: out[0] = tanh(feats[0] @ We^T + be)  (fp32 only)
    G(fH, fL, 32, WeH, WeL, 32, be, nullptr, 0, 0, out, nullptr, nullptr, 256, 32, 256);

    for (int l = 1; l < 6; l++) {
        const int d  = (l - 1 < 2) ? (l - 1) : 2;
        const int i1 = 3 + d, i2 = 9 + d, i3 = d, i4 = 6 + d;
        const int sA = 2 * d, sB = 2 * d + 1;

        // 1. E = tanh(feats_l @ We) : split + fp32
        G(fH + (size_t)l * NN * 32, fL + (size_t)l * NN * 32, 32,
          WeH, WeL, 32, be, nullptr, 0, 0, Ef, Eh, El, 256, 32, 256);

        // big(i1) on concat(E, 0):
        G(Eh, El, 256, c1H + (size_t)i1 * 262144, c1L + (size_t)i1 * 262144, 512,
          rcb1 + i1 * 512, nullptr, 0, 0, nullptr, PAh, PAl, 512, 256, 512);
        G(PAh, PAl, 512, c2H + (size_t)i1 * 262144, c2L + (size_t)i1 * 262144, 512,
          rcb2 + i1 * 512, Ef, 256, 256, nullptr, PBh, PBl, 512, 512, 512);
        G(PBh, PBl, 512, c3H + (size_t)i1 * 131072, c3L + (size_t)i1 * 131072, 512,
          rcb3 + i1 * 256, nullptr, 0, 0, T0f, T0h, T0l, 256, 512, 256);
        // small(i2) -> e2 into X2[:, :256] (split + fp32)
        G(T0h, T0l, 256, s1H + (size_t)i2 * 65536, s1L + (size_t)i2 * 65536, 256,
          rsb1 + i2 * 256, nullptr, 0, 0, nullptr, T1h, T1l, 256, 256, 256);
        G(T1h, T1l, 256, s2H + (size_t)i2 * 65536, s2L + (size_t)i2 * 65536, 256,
          rsb2 + i2 * 256, T0f, 256, 256, nullptr, T2h, T2l, 256, 256, 256);
        G(T2h, T2l, 256, s3H + (size_t)i2 * 65536, s3L + (size_t)i2 * 65536, 256,
          rsb3 + i2 * 256, nullptr, 0, 0, X2f, X2h, X2l, 512, 256, 256);

        // 8. gather messages from previous level's final embeds
        gather_sum<<<NN / 4, 256>>>(out + (size_t)(l - 1) * NN * 256,
                                    pred + (size_t)(l - 1) * NN * 8, Mf, Mh, Ml);
        // small(sA)
        G(Mh, Ml, 256, s1H + (size_t)sA * 65536, s1L + (size_t)sA * 65536, 256,
          rsb1 + sA * 256, nullptr, 0, 0, nullptr, T1h, T1l, 256, 256, 256);
        G(T1h, T1l, 256, s2H + (size_t)sA * 65536, s2L + (size_t)sA * 65536, 256,
          rsb2 + sA * 256, Mf, 256, 256, nullptr, T2h, T2l, 256, 256, 256);
        G(T2h, T2l, 256, s3H + (size_t)sA * 65536, s3L + (size_t)sA * 65536, 256,
          rsb3 + sA * 256, nullptr, 0, 0, T0f, T0h, T0l, 256, 256, 256);
        // small(sB) -> r into X2[:, 256:512] (split + fp32)
        G(T0h, T0l, 256, s1H + (size_t)sB * 65536, s1L + (size_t)sB * 65536, 256,
          rsb1 + sB * 256, nullptr, 0, 0, nullptr, T1h, T1l, 256, 256, 256);
        G(T1h, T1l, 256, s2H + (size_t)sB * 65536, s2L + (size_t)sB * 65536, 256,
          rsb2 + sB * 256, T0f, 256, 256, nullptr, T2h, T2l, 256, 256, 256);
        G(T2h, T2l, 256, s3H + (size_t)sB * 65536, s3L + (size_t)sB * 65536, 256,
          rsb3 + sB * 256, nullptr, 0, 0, X2f + 256, X2h + 256, X2l + 256, 512, 256, 256);

        // big(i3) on x2 = concat(e2, r)
        G(X2h, X2l, 512, c1H + (size_t)i3 * 262144, c1L + (size_t)i3 * 262144, 512,
          rcb1 + i3 * 512, nullptr, 0, 0, nullptr, PAh, PAl, 512, 512, 512);
        G(PAh, PAl, 512, c2H + (size_t)i3 * 262144, c2L + (size_t)i3 * 262144, 512,
          rcb2 + i3 * 512, X2f, 512, 512, nullptr, PBh, PBl, 512, 512, 512);
        G(PBh, PBl, 512, c3H + (size_t)i3 * 131072, c3L + (size_t)i3 * 131072, 512,
          rcb3 + i3 * 256, nullptr, 0, 0, T0f, T0h, T0l, 256, 512, 256);
        // small(i4) -> out[l] (fp32 only)
        G(T0h, T0l, 256, s1H + (size_t)i4 * 65536, s1L + (size_t)i4 * 65536, 256,
          rsb1 + i4 * 256, nullptr, 0, 0, nullptr, T1h, T1l, 256, 256, 256);
        G(T1h, T1l, 256, s2H + (size_t)i4 * 65536, s2L + (size_t)i4 * 65536, 256,
          rsb2 + i4 * 256, T0f, 256, 256, nullptr, T2h, T2l, 256, 256, 256);
        G(T2h, T2l, 256, s3H + (size_t)i4 * 65536, s3L + (size_t)i4 * 65536, 256,
          rsb3 + i4 * 256, nullptr, 0, 0,
          out + (size_t)l * NN * 256, nullptr, nullptr, 256, 256, 256);
    }
}

// round 8
// speedup vs baseline: 1.3756x; 1.2675x over previous
#include <cuda_runtime.h>
#include <cuda_bf16.h>
#include <cstdint>

// ---------------------------------------------------------------------------
// bwd_mpgnn: 6-level GNN stack. Every matmul is C = tanh(A @ W^T + b) with
// residuals folded into producer epilogues. All GEMM operands pre-split into
// bf16 hi/lo planes; GEMM mainloop = cp.async(2-stage) -> ldmatrix -> mma
// (bf16x3: hi*hi + lo*hi + hi*lo, fp32 accumulate).
// Tuned for 2 CTAs/SM: __launch_bounds__(256,2), low-live-register mainloop.
// ---------------------------------------------------------------------------

#define NN 32768
#define PAD 40                        // smem row stride in bf16 elems (conflict-free ldmatrix)
#define TILE_BYTES (128 * PAD * 2)    // 10240 B per 128x32 bf16 plane
#define STAGES 2
#define SMEM_BYTES (STAGES * 4 * TILE_BYTES)   // 81920 B -> 2 CTAs/SM

typedef __nv_bfloat16 bf16;

// ---------------- weight / input split planes ------------------------------
__device__ bf16 g_WeH[8192],      g_WeL[8192];
__device__ bf16 g_fH[6 * NN * 32], g_fL[6 * NN * 32];
__device__ bf16 g_s1H[786432], g_s1L[786432];
__device__ bf16 g_s2H[786432], g_s2L[786432];
__device__ bf16 g_s3H[786432], g_s3L[786432];
__device__ bf16 g_c1H[1572864], g_c1L[1572864];
__device__ bf16 g_c2H[1572864], g_c2L[1572864];
__device__ bf16 g_c3H[786432],  g_c3L[786432];

// ---------------- activation planes ----------------------------------------
__device__ bf16 g_PAh[NN * 512], g_PAl[NN * 512];
__device__ bf16 g_PBh[NN * 512], g_PBl[NN * 512];
__device__ bf16 g_X2h[NN * 512], g_X2l[NN * 512];
__device__ bf16 g_Eh [NN * 256], g_El [NN * 256];
__device__ bf16 g_T0h[NN * 256], g_T0l[NN * 256];
__device__ bf16 g_T1h[NN * 256], g_T1l[NN * 256];
__device__ bf16 g_T2h[NN * 256], g_T2l[NN * 256];
__device__ bf16 g_Mh [NN * 256], g_Ml [NN * 256];
__device__ float g_Ef [NN * 256];
__device__ float g_T0f[NN * 256];
__device__ float g_Mf [NN * 256];
__device__ float g_X2f[NN * 512];

// ---------------- accurate rational tanh (XLA/Eigen) -----------------------
__device__ __forceinline__ float fast_tanh(float x) {
    const float c = 7.90531110763549805f;
    x = fminf(fmaxf(x, -c), c);
    const float x2 = x * x;
    float p = fmaf(x2, -2.76076847742355e-16f, 2.00018790482477e-13f);
    p = fmaf(x2, p, -8.60467152213735e-11f);
    p = fmaf(x2, p, 5.12229709037114e-08f);
    p = fmaf(x2, p, 1.48572235717979e-05f);
    p = fmaf(x2, p, 6.37261928875436e-04f);
    p = fmaf(x2, p, 4.89352455891786e-03f);
    p = x * p;
    float q = fmaf(x2, 1.19825839466702e-06f, 1.18534705686654e-04f);
    q = fmaf(x2, q, 2.26843463243900e-03f);
    q = fmaf(x2, q, 4.89352518554385e-03f);
    return p / q;
}

// ---------------- mma / ldmatrix helpers -----------------------------------
__device__ __forceinline__ void ldm_x4(uint32_t a, uint32_t& r0, uint32_t& r1,
                                       uint32_t& r2, uint32_t& r3) {
    asm volatile("ldmatrix.sync.aligned.m8n8.x4.shared.b16 {%0,%1,%2,%3}, [%4];\n"
                 : "=r"(r0), "=r"(r1), "=r"(r2), "=r"(r3) : "r"(a));
}
__device__ __forceinline__ void mma_bf16(float* c, const uint32_t* a, const uint32_t* b) {
    asm volatile("mma.sync.aligned.m16n8k16.row.col.f32.bf16.bf16.f32 "
                 "{%0,%1,%2,%3}, {%4,%5,%6,%7}, {%8,%9}, {%0,%1,%2,%3};\n"
                 : "+f"(c[0]), "+f"(c[1]), "+f"(c[2]), "+f"(c[3])
                 : "r"(a[0]), "r"(a[1]), "r"(a[2]), "r"(a[3]), "r"(b[0]), "r"(b[1]));
}
__device__ __forceinline__ uint32_t pack2(bf16 a, bf16 b) {
    return ((uint32_t)__bfloat16_as_ushort(b) << 16) | (uint32_t)__bfloat16_as_ushort(a);
}
__device__ __forceinline__ uint32_t split_hi(float2 v, uint32_t& lo) {
    bf16 h0 = __float2bfloat16_rn(v.x), h1 = __float2bfloat16_rn(v.y);
    bf16 l0 = __float2bfloat16_rn(v.x - __bfloat162float(h0));
    bf16 l1 = __float2bfloat16_rn(v.y - __bfloat162float(h1));
    lo = pack2(l0, l1);
    return pack2(h0, h1);
}

// ---------------------------------------------------------------------------
// C = tanh(A @ W^T + bias) [+R on cols<Rcols, added after tanh]
// Outputs (any may be null): Cf fp32, (Ch,Cl) bf16 split planes.
// A as split planes (Ah,Al)[M,K] stride lda; W as (Wh,Wl)[Nout,K] stride ldw.
// BM=BN=128, BK=32, 256 threads (8 warps 2x4), warp tile 64x32. 2-stage cp.async.
// ---------------------------------------------------------------------------
__global__ __launch_bounds__(256, 2) void gemm_tanh(
    const bf16* __restrict__ Ah, const bf16* __restrict__ Al, int lda,
    const bf16* __restrict__ Wh, const bf16* __restrict__ Wl, int ldw,
    const float* __restrict__ bias,
    const float* __restrict__ R, int ldr, int Rcols,
    float* __restrict__ Cf,
    bf16* __restrict__ Ch, bf16* __restrict__ Cl,
    int ldc, int K)
{
    extern __shared__ char smem[];
    const int tid  = threadIdx.x;
    const int lane = tid & 31;
    const int wid  = tid >> 5;
    const int wm   = wid >> 2;   // 0..1
    const int wn   = wid & 3;    // 0..3
    const int mBase = blockIdx.x * 128;
    const int nBase = blockIdx.y * 128;
    const uint32_t sb = (uint32_t)__cvta_generic_to_shared(smem);

    float acc[4][4][4];
#pragma unroll
    for (int i = 0; i < 4; i++)
#pragma unroll
        for (int j = 0; j < 4; j++)
#pragma unroll
            for (int k = 0; k < 4; k++) acc[i][j][k] = 0.f;

    const int T = K >> 5;
    const int seg   = tid & 3;           // 16B segment within 64B row chunk
    const int rhalf = tid >> 2;          // 0..63

    auto issue = [&](int t) {
        const int k0 = (t << 5) + seg * 8;
        const uint32_t stb = sb + (uint32_t)((t & 1) * 4 * TILE_BYTES);
#pragma unroll
        for (int i = 0; i < 8; i++) {
            const int plane = i >> 1;                 // 0:Ah 1:Al 2:Wh 3:Wl
            const int row   = (i & 1) * 64 + rhalf;   // 0..127
            const uint32_t dst = stb + (uint32_t)(plane * TILE_BYTES + row * (PAD * 2) + seg * 16);
            const bf16* src;
            if      (plane == 0) src = Ah + (size_t)(mBase + row) * lda + k0;
            else if (plane == 1) src = Al + (size_t)(mBase + row) * lda + k0;
            else if (plane == 2) src = Wh + (size_t)(nBase + row) * ldw + k0;
            else                 src = Wl + (size_t)(nBase + row) * ldw + k0;
            asm volatile("cp.async.cg.shared.global [%0], [%1], 16;\n" :: "r"(dst), "l"(src));
        }
    };

    // A ldmatrix address (per mf, given plane base)
    const int r16  = ((lane >> 3) & 1) * 8 + (lane & 7);
    const int kofA = (lane >> 4) * 8;
    // B ldmatrix.x4 address (per nf-pair): lanes 0-7 nf0/k0-7, 8-15 nf0/k8-15,
    // 16-23 nf1/k0-7, 24-31 nf1/k8-15
    const int bRow = ((lane >> 4) & 1) * 8 + (lane & 7);
    const int kofB = ((lane >> 3) & 1) * 8;

    auto compute = [&](int s) {
        const uint32_t ab = sb + (uint32_t)(s * 4 * TILE_BYTES);
        const uint32_t bb = ab + 2 * TILE_BYTES;
#pragma unroll
        for (int ks = 0; ks < 2; ks++) {
            uint32_t a1[4][4], a2[4][4], b[4][2];
            // --- load A-hi, B-hi; mma hh ---
#pragma unroll
            for (int mf = 0; mf < 4; mf++) {
                const uint32_t addr = ab +
                    (uint32_t)(((wm * 64 + mf * 16 + r16) * PAD + ks * 16 + kofA) * 2);
                ldm_x4(addr, a1[mf][0], a1[mf][1], a1[mf][2], a1[mf][3]);
            }
#pragma unroll
            for (int p = 0; p < 2; p++) {
                const uint32_t addr = bb +
                    (uint32_t)(((wn * 32 + p * 16 + bRow) * PAD + ks * 16 + kofB) * 2);
                ldm_x4(addr, b[2 * p][0], b[2 * p][1], b[2 * p + 1][0], b[2 * p + 1][1]);
            }
#pragma unroll
            for (int mf = 0; mf < 4; mf++)
#pragma unroll
                for (int nf = 0; nf < 4; nf++) mma_bf16(acc[mf][nf], a1[mf], b[nf]);
            // --- load A-lo; mma lh (uses same B-hi) ---
#pragma unroll
            for (int mf = 0; mf < 4; mf++) {
                const uint32_t addr = ab + TILE_BYTES +
                    (uint32_t)(((wm * 64 + mf * 16 + r16) * PAD + ks * 16 + kofA) * 2);
                ldm_x4(addr, a2[mf][0], a2[mf][1], a2[mf][2], a2[mf][3]);
            }
#pragma unroll
            for (int mf = 0; mf < 4; mf++)
#pragma unroll
                for (int nf = 0; nf < 4; nf++) mma_bf16(acc[mf][nf], a2[mf], b[nf]);
            // --- load B-lo (overwrite B regs); mma hl ---
#pragma unroll
            for (int p = 0; p < 2; p++) {
                const uint32_t addr = bb + TILE_BYTES +
                    (uint32_t)(((wn * 32 + p * 16 + bRow) * PAD + ks * 16 + kofB) * 2);
                ldm_x4(addr, b[2 * p][0], b[2 * p][1], b[2 * p + 1][0], b[2 * p + 1][1]);
            }
#pragma unroll
            for (int mf = 0; mf < 4; mf++)
#pragma unroll
                for (int nf = 0; nf < 4; nf++) mma_bf16(acc[mf][nf], a1[mf], b[nf]);
        }
    };

    // prologue
    issue(0);
    asm volatile("cp.async.commit_group;\n" ::: "memory");
    for (int t = 0; t < T; t++) {
        asm volatile("cp.async.wait_group 0;\n" ::: "memory");
        __syncthreads();
        if (t + 1 < T) {
            issue(t + 1);
            asm volatile("cp.async.commit_group;\n" ::: "memory");
        }
        compute(t & 1);
    }

    // epilogue: bias + tanh (+residual), write fp32 and/or split planes
#pragma unroll
    for (int mf = 0; mf < 4; mf++) {
        const int r0 = mBase + wm * 64 + mf * 16 + (lane >> 2);
#pragma unroll
        for (int nf = 0; nf < 4; nf++) {
            const int c0 = nBase + wn * 32 + nf * 8 + (lane & 3) * 2;
            const float b0 = __ldg(bias + c0), b1 = __ldg(bias + c0 + 1);
            float2 v0 = make_float2(fast_tanh(acc[mf][nf][0] + b0),
                                    fast_tanh(acc[mf][nf][1] + b1));
            float2 v1 = make_float2(fast_tanh(acc[mf][nf][2] + b0),
                                    fast_tanh(acc[mf][nf][3] + b1));
            if (R != nullptr && c0 < Rcols) {
                const float2 ra = *(const float2*)(R + (size_t)r0 * ldr + c0);
                const float2 rb = *(const float2*)(R + (size_t)(r0 + 8) * ldr + c0);
                v0.x += ra.x; v0.y += ra.y;
                v1.x += rb.x; v1.y += rb.y;
            }
            const size_t o0 = (size_t)r0 * ldc + c0;
            const size_t o1 = (size_t)(r0 + 8) * ldc + c0;
            if (Cf != nullptr) {
                *(float2*)(Cf + o0) = v0;
                *(float2*)(Cf + o1) = v1;
            }
            if (Ch != nullptr) {
                uint32_t lo0, lo1;
                const uint32_t hi0 = split_hi(v0, lo0);
                const uint32_t hi1 = split_hi(v1, lo1);
                *(uint32_t*)(Ch + o0) = hi0;  *(uint32_t*)(Cl + o0) = lo0;
                *(uint32_t*)(Ch + o1) = hi1;  *(uint32_t*)(Cl + o1) = lo1;
            }
        }
    }
}

// ---------------- fp32 -> bf16 hi/lo split ---------------------------------
__global__ __launch_bounds__(256) void split_fp32(
    const float* __restrict__ x, bf16* __restrict__ h, bf16* __restrict__ l, int n4)
{
    const int i = blockIdx.x * 256 + threadIdx.x;
    if (i >= n4) return;
    const float4 v = *(const float4*)(x + (size_t)i * 4);
    uint32_t lo0, lo1;
    const uint32_t hi0 = split_hi(make_float2(v.x, v.y), lo0);
    const uint32_t hi1 = split_hi(make_float2(v.z, v.w), lo1);
    *(uint2*)(h + (size_t)i * 4) = make_uint2(hi0, hi1);
    *(uint2*)(l + (size_t)i * 4) = make_uint2(lo0, lo1);
}

// msgs[n,:] = sum_{k<8} src[idx[n,k], :] ; writes fp32 + split planes
__global__ __launch_bounds__(256) void gather_sum(
    const float* __restrict__ src, const int* __restrict__ idx,
    float* __restrict__ dstf, bf16* __restrict__ dsth, bf16* __restrict__ dstl)
{
    const int node = blockIdx.x * 4 + (threadIdx.x >> 6);
    const int lane = threadIdx.x & 63;
    const int* ip = idx + node * 8;
    float4 s = make_float4(0.f, 0.f, 0.f, 0.f);
#pragma unroll
    for (int k = 0; k < 8; k++) {
        const float4 v = *(const float4*)(src + (size_t)ip[k] * 256 + lane * 4);
        s.x += v.x; s.y += v.y; s.z += v.z; s.w += v.w;
    }
    const size_t o = (size_t)node * 256 + lane * 4;
    *(float4*)(dstf + o) = s;
    uint32_t lo0, lo1;
    const uint32_t hi0 = split_hi(make_float2(s.x, s.y), lo0);
    const uint32_t hi1 = split_hi(make_float2(s.z, s.w), lo1);
    *(uint2*)(dsth + o) = make_uint2(hi0, hi1);
    *(uint2*)(dstl + o) = make_uint2(lo0, lo1);
}

extern "C" void kernel_launch(void* const* d_in, const int* in_sizes, int n_in,
                              void* d_out, int out_size)
{
    const float* feats = (const float*)d_in[0];
    const int*   pred  = (const int*)  d_in[1];
    const float* WeF   = (const float*)d_in[2];
    const float* be    = (const float*)d_in[3];
    const float* rsW1  = (const float*)d_in[4];
    const float* rsb1  = (const float*)d_in[5];
    const float* rsW2  = (const float*)d_in[6];
    const float* rsb2  = (const float*)d_in[7];
    const float* rsW3  = (const float*)d_in[8];
    const float* rsb3  = (const float*)d_in[9];
    const float* rcW1  = (const float*)d_in[10];
    const float* rcb1  = (const float*)d_in[11];
    const float* rcW2  = (const float*)d_in[12];
    const float* rcb2  = (const float*)d_in[13];
    const float* rcW3  = (const float*)d_in[14];
    const float* rcb3  = (const float*)d_in[15];
    float* out = (float*)d_out;

    bf16 *WeH,*WeL,*fH,*fL,*s1H,*s1L,*s2H,*s2L,*s3H,*s3L,*c1H,*c1L,*c2H,*c2L,*c3H,*c3L;
    bf16 *PAh,*PAl,*PBh,*PBl,*X2h,*X2l,*Eh,*El,*T0h,*T0l,*T1h,*T1l,*T2h,*T2l,*Mh,*Ml;
    float *Ef,*T0f,*Mf,*X2f;
    cudaGetSymbolAddress((void**)&WeH, g_WeH); cudaGetSymbolAddress((void**)&WeL, g_WeL);
    cudaGetSymbolAddress((void**)&fH,  g_fH);  cudaGetSymbolAddress((void**)&fL,  g_fL);
    cudaGetSymbolAddress((void**)&s1H, g_s1H); cudaGetSymbolAddress((void**)&s1L, g_s1L);
    cudaGetSymbolAddress((void**)&s2H, g_s2H); cudaGetSymbolAddress((void**)&s2L, g_s2L);
    cudaGetSymbolAddress((void**)&s3H, g_s3H); cudaGetSymbolAddress((void**)&s3L, g_s3L);
    cudaGetSymbolAddress((void**)&c1H, g_c1H); cudaGetSymbolAddress((void**)&c1L, g_c1L);
    cudaGetSymbolAddress((void**)&c2H, g_c2H); cudaGetSymbolAddress((void**)&c2L, g_c2L);
    cudaGetSymbolAddress((void**)&c3H, g_c3H); cudaGetSymbolAddress((void**)&c3L, g_c3L);
    cudaGetSymbolAddress((void**)&PAh, g_PAh); cudaGetSymbolAddress((void**)&PAl, g_PAl);
    cudaGetSymbolAddress((void**)&PBh, g_PBh); cudaGetSymbolAddress((void**)&PBl, g_PBl);
    cudaGetSymbolAddress((void**)&X2h, g_X2h); cudaGetSymbolAddress((void**)&X2l, g_X2l);
    cudaGetSymbolAddress((void**)&Eh,  g_Eh);  cudaGetSymbolAddress((void**)&El,  g_El);
    cudaGetSymbolAddress((void**)&T0h, g_T0h); cudaGetSymbolAddress((void**)&T0l, g_T0l);
    cudaGetSymbolAddress((void**)&T1h, g_T1h); cudaGetSymbolAddress((void**)&T1l, g_T1l);
    cudaGetSymbolAddress((void**)&T2h, g_T2h); cudaGetSymbolAddress((void**)&T2l, g_T2l);
    cudaGetSymbolAddress((void**)&Mh,  g_Mh);  cudaGetSymbolAddress((void**)&Ml,  g_Ml);
    cudaGetSymbolAddress((void**)&Ef,  g_Ef);  cudaGetSymbolAddress((void**)&T0f, g_T0f);
    cudaGetSymbolAddress((void**)&Mf,  g_Mf);  cudaGetSymbolAddress((void**)&X2f, g_X2f);

    cudaFuncSetAttribute(gemm_tanh, cudaFuncAttributeMaxDynamicSharedMemorySize, SMEM_BYTES);

    auto SP = [&](const float* s, bf16* h, bf16* l, int n) {
        split_fp32<<<(n / 4 + 255) / 256, 256>>>(s, h, l, n / 4);
    };
    SP(WeF, WeH, WeL, 8192);
    SP(feats, fH, fL, 6 * NN * 32);
    SP(rsW1, s1H, s1L, 786432);
    SP(rsW2, s2H, s2L, 786432);
    SP(rsW3, s3H, s3L, 786432);
    SP(rcW1, c1H, c1L, 1572864);
    SP(rcW2, c2H, c2L, 1572864);
    SP(rcW3, c3H, c3L, 786432);

    auto G = [&](const bf16* Ah, const bf16* Al, int lda,
                 const bf16* Wh, const bf16* Wl, int ldw,
                 const float* b,
                 const float* R, int ldr, int Rcols,
                 float* Cf, bf16* Ch, bf16* Cl, int ldc,
                 int K, int Nout) {
        dim3 grid(NN / 128, Nout / 128);
        gemm_tanh<<<grid, 256, SMEM_BYTES>>>(Ah, Al, lda, Wh, Wl, ldw, b,
                                             R, ldr, Rcols, Cf, Ch, Cl, ldc, K);
    };

    // level 0: out[0] = tanh(feats[0] @ We^T + be)  (fp32 only)
    G(fH, fL, 32, WeH, WeL, 32, be, nullptr, 0, 0, out, nullptr, nullptr, 256, 32, 256);

    for (int l = 1; l < 6; l++) {
        const int d  = (l - 1 < 2) ? (l - 1) : 2;
        const int i1 = 3 + d, i2 = 9 + d, i3 = d, i4 = 6 + d;
        const int sA = 2 * d, sB = 2 * d + 1;

        // E = tanh(feats_l @ We): split + fp32
        G(fH + (size_t)l * NN * 32, fL + (size_t)l * NN * 32, 32,
          WeH, WeL, 32, be, nullptr, 0, 0, Ef, Eh, El, 256, 32, 256);

        // big(i1) on concat(E, 0): layer1 K=256 (zero half skipped)
        G(Eh, El, 256, c1H + (size_t)i1 * 262144, c1L + (size_t)i1 * 262144, 512,
          rcb1 + i1 * 512, nullptr, 0, 0, nullptr, PAh, PAl, 512, 256, 512);
        G(PAh, PAl, 512, c2H + (size_t)i1 * 262144, c2L + (size_t)i1 * 262144, 512,
          rcb2 + i1 * 512, Ef, 256, 256, nullptr, PBh, PBl, 512, 512, 512);
        G(PBh, PBl, 512, c3H + (size_t)i1 * 131072, c3L + (size_t)i1 * 131072, 512,
          rcb3 + i1 * 256, nullptr, 0, 0, T0f, T0h, T0l, 256, 512, 256);
        // small(i2) -> e2 into X2[:, :256] (split + fp32)
        G(T0h, T0l, 256, s1H + (size_t)i2 * 65536, s1L + (size_t)i2 * 65536, 256,
          rsb1 + i2 * 256, nullptr, 0, 0, nullptr, T1h, T1l, 256, 256, 256);
        G(T1h, T1l, 256, s2H + (size_t)i2 * 65536, s2L + (size_t)i2 * 65536, 256,
          rsb2 + i2 * 256, T0f, 256, 256, nullptr, T2h, T2l, 256, 256, 256);
        G(T2h, T2l, 256, s3H + (size_t)i2 * 65536, s3L + (size_t)i2 * 65536, 256,
          rsb3 + i2 * 256, nullptr, 0, 0, X2f, X2h, X2l, 512, 256, 256);

        // gather messages from previous level's final embeds
        gather_sum<<<NN / 4, 256>>>(out + (size_t)(l - 1) * NN * 256,
                                    pred + (size_t)(l - 1) * NN * 8, Mf, Mh, Ml);
        // small(sA)
        G(Mh, Ml, 256, s1H + (size_t)sA * 65536, s1L + (size_t)sA * 65536, 256,
          rsb1 + sA * 256, nullptr, 0, 0, nullptr, T1h, T1l, 256, 256, 256);
        G(T1h, T1l, 256, s2H + (size_t)sA * 65536, s2L + (size_t)sA * 65536, 256,
          rsb2 + sA * 256, Mf, 256, 256, nullptr, T2h, T2l, 256, 256, 256);
        G(T2h, T2l, 256, s3H + (size_t)sA * 65536, s3L + (size_t)sA * 65536, 256,
          rsb3 + sA * 256, nullptr, 0, 0, T0f, T0h, T0l, 256, 256, 256);
        // small(sB) -> r into X2[:, 256:512] (split + fp32)
        G(T0h, T0l, 256, s1H + (size_t)sB * 65536, s1L + (size_t)sB * 65536, 256,
          rsb1 + sB * 256, nullptr, 0, 0, nullptr, T1h, T1l, 256, 256, 256);
        G(T1h, T1l, 256, s2H + (size_t)sB * 65536, s2L + (size_t)sB * 65536, 256,
          rsb2 + sB * 256, T0f, 256, 256, nullptr, T2h, T2l, 256, 256, 256);
        G(T2h, T2l, 256, s3H + (size_t)sB * 65536, s3L + (size_t)sB * 65536, 256,
          rsb3 + sB * 256, nullptr, 0, 0, X2f + 256, X2h + 256, X2l + 256, 512, 256, 256);

        // big(i3) on x2 = concat(e2, r)
        G(X2h, X2l, 512, c1H + (size_t)i3 * 262144, c1L + (size_t)i3 * 262144, 512,
          rcb1 + i3 * 512, nullptr, 0, 0, nullptr, PAh, PAl, 512, 512, 512);
        G(PAh, PAl, 512, c2H + (size_t)i3 * 262144, c2L + (size_t)i3 * 262144, 512,
          rcb2 + i3 * 512, X2f, 512, 512, nullptr, PBh, PBl, 512, 512, 512);
        G(PBh, PBl, 512, c3H + (size_t)i3 * 131072, c3L + (size_t)i3 * 131072, 512,
          rcb3 + i3 * 256, nullptr, 0, 0, T0f, T0h, T0l, 256, 512, 256);
        // small(i4) -> out[l] (fp32 only)
        G(T0h, T0l, 256, s1H + (size_t)i4 * 65536, s1L + (size_t)i4 * 65536, 256,
          rsb1 + i4 * 256, nullptr, 0, 0, nullptr, T1h, T1l, 256, 256, 256);
        G(T1h, T1l, 256, s2H + (size_t)i4 * 65536, s2L + (size_t)i4 * 65536, 256,
          rsb2 + i4 * 256, T0f, 256, 256, nullptr, T2h, T2l, 256, 256, 256);
        G(T2h, T2l, 256, s3H + (size_t)i4 * 65536, s3L + (size_t)i4 * 65536, 256,
          rsb3 + i4 * 256, nullptr, 0, 0,
          out + (size_t)l * NN * 256, nullptr, nullptr, 256, 256, 256);
    }
}